// round 7
// baseline (speedup 1.0000x reference)
#include <cuda_runtime.h>

// Shapes fixed by the problem: B=4, T=2048, D=768 -> E=2*D=1536, H=256.
#define B_DIM 4
#define T_DIM 2048
#define E_DIM 1536
#define H_DIM 256

#define NTHREADS    384                   // one thread per float4 column (E/4)
#define COLS4       (E_DIM / 4)           // 384
#define N_BLOCKS    256                   // single wave at 2 blocks/SM
#define CHUNK_ROWS  16                    // stealing grain
#define CHUNKS_PER_B (T_DIM / CHUNK_ROWS) // 128
#define N_CHUNKS    (B_DIM * CHUNKS_PER_B)// 512
#define N_TAIL      64                    // blocks that run the GEMV tail
#define D_CHUNK     (E_DIM / N_TAIL)      // 24 W1 rows per tail block
#define N_HBANK     8
#define W1_BYTES    (E_DIM * H_DIM * 4)   // 1.5 MB

// Scratch: __device__ globals (allocation-free rule). Statics start zero;
// tail blocks zero the colsum slices they consume, the epilogue zeroes the
// hbanks + counters, so every graph replay sees clean state.
__device__ float             g_colsum[B_DIM * E_DIM];
__device__ float             g_hbank[N_HBANK][B_DIM][H_DIM];
__device__ unsigned          g_ticket;
__device__ volatile unsigned g_c1;
__device__ unsigned          g_c2;

__global__ void __launch_bounds__(NTHREADS, 2)
curiosity_fused(const float* __restrict__ x,
                const float* __restrict__ W1,
                const float* __restrict__ b1,
                const float* __restrict__ W2,
                const float* __restrict__ b2,
                float* __restrict__ out, int out_size) {
    const int tid = threadIdx.x;
    const int bid = blockIdx.x;

    // Prefetch this block's 6KB slice of W1 into L2 so the tail GEMV is warm.
    {
        const char* wp = (const char*)W1 + (size_t)bid * (W1_BYTES / N_BLOCKS);
        if (tid < (W1_BYTES / N_BLOCKS) / 128)
            asm volatile("prefetch.global.L2 [%0];" :: "l"(wp + tid * 128));
    }

    // ---------------- Phase 1: work-stealing column sum ---------------------
    // Chunks = 16 rows of one batch element. Thread owns float4 column tid.
    // Ticket order makes b monotone per block -> single accumulator with
    // flush-on-b-change keeps atomic traffic low and balance near-perfect.
    {
        __shared__ unsigned s_ticket;
        int    cur_b = -1;
        float4 acc   = make_float4(0.f, 0.f, 0.f, 0.f);

        for (;;) {
            if (tid == 0) s_ticket = atomicAdd(&g_ticket, 1u);
            __syncthreads();
            unsigned t = s_ticket;
            __syncthreads();               // protect s_ticket before next write
            if (t >= N_CHUNKS) break;

            const int b  = t / CHUNKS_PER_B;
            const int r0 = (t % CHUNKS_PER_B) * CHUNK_ROWS;

            if (b != cur_b) {
                if (cur_b >= 0) {
                    float* dst = &g_colsum[cur_b * E_DIM + tid * 4];
                    atomicAdd(dst + 0, acc.x);
                    atomicAdd(dst + 1, acc.y);
                    atomicAdd(dst + 2, acc.z);
                    atomicAdd(dst + 3, acc.w);
                }
                acc   = make_float4(0.f, 0.f, 0.f, 0.f);
                cur_b = b;
            }

            const float4* xp = reinterpret_cast<const float4*>(x)
                             + (size_t)(b * T_DIM + r0) * COLS4 + tid;
#pragma unroll
            for (int h = 0; h < CHUNK_ROWS / 8; h++) {
                float4 v[8];                     // 8 loads in flight per batch
#pragma unroll
                for (int i = 0; i < 8; i++)
                    v[i] = xp[(size_t)(h * 8 + i) * COLS4];
#pragma unroll
                for (int i = 0; i < 8; i++) {
                    acc.x += v[i].x; acc.y += v[i].y;
                    acc.z += v[i].z; acc.w += v[i].w;
                }
            }
        }
        if (cur_b >= 0) {
            float* dst = &g_colsum[cur_b * E_DIM + tid * 4];
            atomicAdd(dst + 0, acc.x);
            atomicAdd(dst + 1, acc.y);
            atomicAdd(dst + 2, acc.z);
            atomicAdd(dst + 3, acc.w);
        }

        __syncthreads();                   // all block atomics issued
        if (tid == 0) {
            __threadfence();               // release colsum
            atomicAdd((unsigned*)&g_c1, 1u);
        }
    }

    // 192 non-tail blocks are done — exit, free the SMs.
    if (bid >= N_TAIL) return;

    // ---------------- Barrier: wait for all phase-1 contributions ----------
    if (tid == 0) {
        while (g_c1 < N_BLOCKS) { }        // volatile poll
        __threadfence();                   // acquire
    }
    __syncthreads();

    // ---------------- Phase 2: GEMV1 (64 tail blocks x 24 W1 rows) ---------
    __shared__ float s[B_DIM][D_CHUNK];
    const int d0 = bid * D_CHUNK;
    {
        if (tid < B_DIM * D_CHUNK) {       // 96 threads
            int b = tid / D_CHUNK, dd = tid % D_CHUNK;
            s[b][dd] = g_colsum[b * E_DIM + d0 + dd] * (1.0f / (float)T_DIM);
        }
        __syncthreads();

        // Distributed reset: this block is the only consumer of its slice.
        if (tid >= 256 && tid < 256 + B_DIM * D_CHUNK) {
            int i = tid - 256;
            int b = i / D_CHUNK, dd = i % D_CHUNK;
            g_colsum[b * E_DIM + d0 + dd] = 0.0f;
        }

        if (tid < H_DIM) {
            const int j = tid;
            float a0 = 0.f, a1 = 0.f, a2 = 0.f, a3 = 0.f;
#pragma unroll 8
            for (int dd = 0; dd < D_CHUNK; dd++) {
                float ww = W1[(size_t)(d0 + dd) * H_DIM + j];
                a0 = fmaf(s[0][dd], ww, a0);
                a1 = fmaf(s[1][dd], ww, a1);
                a2 = fmaf(s[2][dd], ww, a2);
                a3 = fmaf(s[3][dd], ww, a3);
            }
            const int bank = bid & (N_HBANK - 1);
            atomicAdd(&g_hbank[bank][0][j], a0);
            atomicAdd(&g_hbank[bank][1][j], a1);
            atomicAdd(&g_hbank[bank][2][j], a2);
            atomicAdd(&g_hbank[bank][3][j], a3);
        }
    }

    // ---------------- Phase 3: epilogue in the LAST-arriving tail block ----
    __syncthreads();
    __shared__ unsigned s_last;
    if (tid == 0) {
        __threadfence();                   // release hidden partials
        s_last = (atomicAdd(&g_c2, 1u) == N_TAIL - 1u) ? 1u : 0u;
    }
    __syncthreads();
    if (!s_last) return;

    if (tid == 0) __threadfence();         // acquire all hidden partials
    __syncthreads();

    __shared__ float red[B_DIM][8];
    if (tid < H_DIM) {
        const int j    = tid;
        const int lane = j & 31, warp = j >> 5;
        float w2 = W2[j];
        float bb = b1[j];
        float v[B_DIM];
#pragma unroll
        for (int b = 0; b < B_DIM; b++) {
            float h = bb;
#pragma unroll
            for (int p = 0; p < N_HBANK; p++) h += g_hbank[p][b][j];
            v[b] = fmaxf(h, 0.0f) * w2;
        }
#pragma unroll
        for (int off = 16; off > 0; off >>= 1)
#pragma unroll
            for (int b = 0; b < B_DIM; b++)
                v[b] += __shfl_down_sync(0xffffffffu, v[b], off);
        if (lane == 0)
#pragma unroll
            for (int b = 0; b < B_DIM; b++) red[b][warp] = v[b];
    }
    __syncthreads();

    if (tid < B_DIM && tid < out_size) {
        float sm = 0.f;
#pragma unroll
        for (int w8 = 0; w8 < 8; w8++) sm += red[tid][w8];
        out[tid] = sm + b2[0];
    }
    // best_action_idx slot: argmax over 32 bit-identical entropies == 0
    // always (int 0 == float 0.0 bit pattern). Zero-fill the rest.
    for (int i = B_DIM + tid; i < out_size; i += NTHREADS)
        out[i] = 0.0f;

    // Reset remaining scratch for the next graph replay.
    for (int i = tid; i < N_HBANK * B_DIM * H_DIM; i += NTHREADS)
        ((float*)g_hbank)[i] = 0.0f;
    __syncthreads();
    if (tid == 0) { g_c2 = 0u; g_ticket = 0u; g_c1 = 0u; __threadfence(); }
}

extern "C" void kernel_launch(void* const* d_in, const int* in_sizes, int n_in,
                              void* d_out, int out_size) {
    const float* x  = (const float*)d_in[0];
    const float* W1 = (const float*)d_in[1];
    const float* b1 = (const float*)d_in[2];
    const float* W2 = (const float*)d_in[3];
    const float* b2 = (const float*)d_in[4];
    float* out = (float*)d_out;

    curiosity_fused<<<N_BLOCKS, NTHREADS>>>(x, W1, b1, W2, b2, out, out_size);
}

// round 8
// speedup vs baseline: 1.4877x; 1.4877x over previous
#include <cuda_runtime.h>

// Shapes fixed by the problem: B=4, T=2048, D=768 -> E=2*D=1536, H=256.
#define B_DIM 4
#define T_DIM 2048
#define E_DIM 1536
#define H_DIM 256

#define NT_CHUNKS 32
#define T_CHUNK   (T_DIM / NT_CHUNKS)      // 64
#define COLS4     (E_DIM / 4)              // 384 float4 per (b,t) row
#define CB_CHUNKS 6                        // 6 * 256 = 1536 = B*COLS4
#define N_BLOCKS  (CB_CHUNKS * NT_CHUNKS)  // 192
#define N_TAIL    16
#define D_CHUNK   (E_DIM / N_TAIL)         // 96

// Scratch: __device__ globals (allocation-free rule). Statics start zero;
// tail blocks zero the colsum slices they consume and the last-arriver
// resets the counters, so every graph replay sees clean state.
// g_hpart is unconditionally overwritten each call -> needs no reset.
__device__ float             g_colsum[B_DIM * E_DIM];
__device__ float             g_hpart[N_TAIL][B_DIM][H_DIM];
__device__ volatile unsigned g_c1;
__device__ unsigned          g_c2;

__global__ void __launch_bounds__(256, 2)
curiosity_fused(const float* __restrict__ x,
                const float* __restrict__ W1,
                const float* __restrict__ b1,
                const float* __restrict__ W2,
                const float* __restrict__ b2,
                float* __restrict__ out, int out_size) {
    const int tid = threadIdx.x;
    const int bid = blockIdx.x;

    // ---------------- Phase 1: column sum over T (all 192 blocks) ----------
    // R2's winning shape: 256 threads x float4 col chunk, 64 rows/block,
    // regs~128 lets ptxas keep many LDG.128 in flight.
    {
        int cb = bid % CB_CHUNKS;          // which 256-wide float4 col chunk
        int tb = bid / CB_CHUNKS;          // which T chunk
        int gc = cb * 256 + tid;           // global (b, c4) in [0, 1536)
        int b  = gc / COLS4;
        int c4 = gc % COLS4;
        int t0 = tb * T_CHUNK;

        const float4* xp = reinterpret_cast<const float4*>(x)
                         + (size_t)(b * T_DIM + t0) * COLS4 + c4;

        float4 acc = make_float4(0.f, 0.f, 0.f, 0.f);
#pragma unroll 8
        for (int t = 0; t < T_CHUNK; t++) {
            float4 v = xp[(size_t)t * COLS4];
            acc.x += v.x; acc.y += v.y; acc.z += v.z; acc.w += v.w;
        }
        float* dst = &g_colsum[gc * 4];
        atomicAdd(dst + 0, acc.x);
        atomicAdd(dst + 1, acc.y);
        atomicAdd(dst + 2, acc.z);
        atomicAdd(dst + 3, acc.w);

        __syncthreads();                   // all block atomics issued
        if (tid == 0) {
            __threadfence();               // release colsum before counter
            atomicAdd((unsigned*)&g_c1, 1u);
        }
    }

    // 176 non-tail blocks exit immediately — no barrier cost for them.
    if (bid >= N_TAIL) return;

    // ---------------- Phase 2: GEMV1 tail (blocks 0..15) -------------------
    __shared__ float s[B_DIM][D_CHUNK];
    const int j  = tid;                    // hidden index, 256 threads = H
    const int d0 = bid * D_CHUNK;

    // Preload this block's W1 chunk into registers BEFORE spinning so the
    // loads overlap with the remaining colsum DRAM traffic (R2 trick).
    float w[D_CHUNK];
#pragma unroll
    for (int dd = 0; dd < D_CHUNK; dd++)
        w[dd] = W1[(size_t)(d0 + dd) * H_DIM + j];

    if (tid == 0) {
        while (g_c1 < N_BLOCKS) { }        // volatile poll (no L2 RMW spam)
        __threadfence();                   // acquire
    }
    __syncthreads();

    // Means for this d-chunk into smem, then distributed reset of the slice
    // (this block is its only consumer).
    for (int i = tid; i < B_DIM * D_CHUNK; i += 256) {
        int b = i / D_CHUNK, dd = i % D_CHUNK;
        float cs = g_colsum[b * E_DIM + d0 + dd];
        s[b][dd] = cs * (1.0f / (float)T_DIM);
        g_colsum[b * E_DIM + d0 + dd] = 0.0f;
    }
    __syncthreads();

    float a0 = 0.f, a1 = 0.f, a2 = 0.f, a3 = 0.f;
#pragma unroll
    for (int dd = 0; dd < D_CHUNK; dd++) {
        float ww = w[dd];
        a0 = fmaf(s[0][dd], ww, a0);
        a1 = fmaf(s[1][dd], ww, a1);
        a2 = fmaf(s[2][dd], ww, a2);
        a3 = fmaf(s[3][dd], ww, a3);
    }
    g_hpart[bid][0][j] = a0;
    g_hpart[bid][1][j] = a1;
    g_hpart[bid][2][j] = a2;
    g_hpart[bid][3][j] = a3;

    // ---------------- Phase 3: epilogue in the LAST-arriving tail block ----
    __syncthreads();
    __shared__ unsigned s_last;
    if (tid == 0) {
        __threadfence();                   // release hidden partials
        s_last = (atomicAdd(&g_c2, 1u) == N_TAIL - 1u) ? 1u : 0u;
    }
    __syncthreads();
    if (!s_last) return;

    if (tid == 0) __threadfence();         // acquire all hidden partials
    __syncthreads();

    __shared__ float red[B_DIM][8];
    {
        const int lane = j & 31, warp = j >> 5;
        float w2 = W2[j];
        float bb = b1[j];
        float v[B_DIM];
#pragma unroll
        for (int b = 0; b < B_DIM; b++) {
            float h = bb;
#pragma unroll
            for (int p = 0; p < N_TAIL; p++) h += g_hpart[p][b][j];
            v[b] = fmaxf(h, 0.0f) * w2;
        }
#pragma unroll
        for (int off = 16; off > 0; off >>= 1)
#pragma unroll
            for (int b = 0; b < B_DIM; b++)
                v[b] += __shfl_down_sync(0xffffffffu, v[b], off);
        if (lane == 0)
#pragma unroll
            for (int b = 0; b < B_DIM; b++) red[b][warp] = v[b];
    }
    __syncthreads();

    if (tid < B_DIM && tid < out_size) {
        float sm = 0.f;
#pragma unroll
        for (int w8 = 0; w8 < 8; w8++) sm += red[tid][w8];
        out[tid] = sm + b2[0];
    }
    // best_action_idx slot: argmax over 32 bit-identical entropies == 0
    // always (int 0 == float 0.0 bit pattern). Zero-fill the rest.
    for (int i = B_DIM + tid; i < out_size; i += 256)
        out[i] = 0.0f;

    __syncthreads();
    if (tid == 0) { g_c2 = 0u; g_c1 = 0u; __threadfence(); }
}

extern "C" void kernel_launch(void* const* d_in, const int* in_sizes, int n_in,
                              void* d_out, int out_size) {
    const float* x  = (const float*)d_in[0];
    const float* W1 = (const float*)d_in[1];
    const float* b1 = (const float*)d_in[2];
    const float* W2 = (const float*)d_in[3];
    const float* b2 = (const float*)d_in[4];
    float* out = (float*)d_out;

    curiosity_fused<<<N_BLOCKS, 256>>>(x, W1, b1, W2, b2, out, out_size);
}